// round 2
// baseline (speedup 1.0000x reference)
#include <cuda_runtime.h>
#include <cuda_bf16.h>

// ---------------------------------------------------------------------------
// Problem constants
// ---------------------------------------------------------------------------
#define BATCH 8
#define CHANNELS 1024
#define HW 2304           // 48*48
#define POOL_P 576        // 24*24
#define POS_TOTAL (BATCH*POOL_P*POOL_P)   // 2,654,208
#define EPS_L2 1e-6f
#define EPS_MM 1e-5f

typedef unsigned long long u64;

// ---------------------------------------------------------------------------
// Scratch (device globals; no allocation allowed)
// ---------------------------------------------------------------------------
// A in MMA-fragment layout: [b][rowblk 18][ktile 128][mtile 8][lane 32][4]
// B in MMA-fragment layout: [b][colblk 18][ktile 128][ntile 16][lane 32][2]
__device__ float g_A[BATCH * HW * CHANNELS];
__device__ float g_B[BATCH * HW * CHANNELS];
__device__ float g_invnA[BATCH * HW];
__device__ float g_invnB[BATCH * HW];
__device__ float g_cpool[POS_TOTAL];          // pooled corr / conv3 out (reused)
__device__ float g_x1[BATCH * 10 * POOL_P * POOL_P];
__device__ float g_x2[BATCH * 10 * POOL_P * POOL_P];
__device__ float g_amax[BATCH * POOL_P];
__device__ float g_bmax[BATCH * POOL_P];

// ---------------------------------------------------------------------------
// Helpers
// ---------------------------------------------------------------------------
__device__ __forceinline__ unsigned smem_u32(const void* p) {
    return (unsigned)__cvta_generic_to_shared(p);
}
__device__ __forceinline__ u64 pack2(float a, float b) {
    u64 r; asm("mov.b64 %0, {%1, %2};" : "=l"(r) : "f"(a), "f"(b)); return r;
}
__device__ __forceinline__ void fma2(u64& d, u64 a, u64 b) {
    asm("fma.rn.f32x2 %0, %1, %2, %0;" : "+l"(d) : "l"(a), "l"(b));
}
__device__ __forceinline__ float2 unpack2(u64 v) {
    float2 r; asm("mov.b64 {%0, %1}, %2;" : "=f"(r.x), "=f"(r.y) : "l"(v)); return r;
}

// ---------------------------------------------------------------------------
// 1) inverse L2 norm per (b, hw) for both feature tensors
// ---------------------------------------------------------------------------
__global__ void invnorm_kernel(const float* __restrict__ A, const float* __restrict__ B) {
    int t = blockIdx.x * blockDim.x + threadIdx.x;
    if (t >= 2 * BATCH * HW) return;
    const float* f = (t < BATCH * HW) ? A : B;
    float* o = (t < BATCH * HW) ? g_invnA : g_invnB;
    int idx = t % (BATCH * HW);
    int b = idx / HW, hw = idx % HW;
    const float* p = f + (size_t)b * CHANNELS * HW + hw;
    float s = 0.f;
#pragma unroll 8
    for (int c = 0; c < CHANNELS; ++c) {
        float v = p[(size_t)c * HW];
        s = fmaf(v, v, s);
    }
    o[idx] = rsqrtf(s + EPS_L2);
}

// ---------------------------------------------------------------------------
// 2) transpose + normalize + tf32-round, writing MMA-fragment-ordered layout.
//    p' permutation (pool-group-major) applied to the position dimension.
//    MODE 0: A layout (16x8 tiles, 4 floats/lane)
//    MODE 1: B layout (8x8 tiles,  2 floats/lane)
// ---------------------------------------------------------------------------
template <int MODE>
__global__ __launch_bounds__(256) void transnorm_kernel(
    const float* __restrict__ f, const float* __restrict__ invn,
    float* __restrict__ out) {
    __shared__ float sm[32][33];
    int b = blockIdx.z;
    int pb = blockIdx.x;        // block of 32 permuted positions (0..71)
    int c0 = blockIdx.y * 32;   // channel block
    int g0 = pb * 8;            // first 2x2 pool group
    int hbase = (g0 / 24) * 2;
    int wbase = (g0 % 24) * 2;
    int tid = threadIdx.x;

    // read 32 channels x 32 positions (2 rows x 16 cols of the 48x48 grid)
    for (int idx = tid; idx < 1024; idx += 256) {
        int ci = idx >> 5, pos = idx & 31;
        int hh = pos >> 4, ww = pos & 15;
        int hw = (hbase + hh) * 48 + wbase + ww;
        float v = f[((size_t)b * CHANNELS + c0 + ci) * HW + hw] * invn[b * HW + hw];
        unsigned t; asm("cvt.rna.tf32.f32 %0, %1;" : "=r"(t) : "f"(v));
        int p_in = ((ww >> 1) << 2) | (hh << 1) | (ww & 1);   // p' within block
        sm[p_in][ci] = __uint_as_float(t);
    }
    __syncthreads();

    int p0 = pb * 32;
    if (MODE == 0) {
        // A: one float4 line per thread (rows r,r+8 x cols c,c+4 of a 16x8 tile)
        int mt = tid >> 7, kt = (tid >> 5) & 3, lane = tid & 31;
        int rowin = lane >> 2, colin = lane & 3;
        float4 v;
        v.x = sm[mt * 16 + rowin][kt * 8 + colin];
        v.y = sm[mt * 16 + rowin + 8][kt * 8 + colin];
        v.z = sm[mt * 16 + rowin][kt * 8 + colin + 4];
        v.w = sm[mt * 16 + rowin + 8][kt * 8 + colin + 4];
        int rowblk = p0 >> 7;
        int mtile_g = ((p0 >> 4) & 7) + mt;
        int ktile_g = (c0 >> 3) + kt;
        size_t off = ((((size_t)b * 18 + rowblk) * 128 + ktile_g) * 8 + mtile_g) * 128
                     + lane * 4;
        *(float4*)(out + off) = v;
    } else {
        // B: two float2 lines per thread (rows k,k+4 of an 8x8 tile)
        int colblk = p0 >> 7;
#pragma unroll
        for (int i = 0; i < 2; ++i) {
            int id = tid + i * 256;
            int nt = id >> 7, kt = (id >> 5) & 3, lane = id & 31;
            int rowin = lane >> 2, colin = lane & 3;
            float2 v;
            v.x = sm[nt * 8 + rowin][kt * 8 + colin];
            v.y = sm[nt * 8 + rowin][kt * 8 + colin + 4];
            int ntile_g = ((p0 >> 3) & 15) + nt;
            int ktile_g = (c0 >> 3) + kt;
            size_t off = ((((size_t)b * 18 + colblk) * 128 + ktile_g) * 16 + ntile_g) * 64
                         + lane * 2;
            *(float2*)(out + off) = v;
        }
    }
}

// ---------------------------------------------------------------------------
// 3) batched TF32 GEMM (mma.sync.m16n8k8) + fused 4x4 max-pool + relu/L2.
//    Operands pre-arranged in fragment order -> LDS.128 / LDS.64 per fragment.
// ---------------------------------------------------------------------------
#define GBK 32
#define STAGE_FLOATS 4096   // 4 ktiles * 1024 floats

__global__ __launch_bounds__(256) void gemm_pool_kernel(
    const float* __restrict__ A, const float* __restrict__ B,
    float* __restrict__ out) {
    extern __shared__ char smem_raw[];
    float* As = (float*)smem_raw;            // [2][4096]
    float* Bs = As + 2 * STAGE_FLOATS;       // [2][4096]
    float* Cs = (float*)smem_raw;            // reused: [128][132]

    int b = blockIdx.z;
    const float* Ag = A + (size_t)b * HW * CHANNELS + (size_t)blockIdx.y * 18 * 0  // dummy
                        + (size_t)blockIdx.y * 128 * 1024;   // rowblk stride = 128 ktiles * 1024
    const float* Bg = B + (size_t)b * HW * CHANNELS + (size_t)blockIdx.x * 128 * 1024;

    int tid = threadIdx.x, lane = tid & 31, wid = tid >> 5;
    int wm = wid >> 2, wn = wid & 3;   // 2 x 4 warp grid, warp tile 64x32

    float acc[4][4][4];
#pragma unroll
    for (int i = 0; i < 4; ++i)
#pragma unroll
        for (int j = 0; j < 4; ++j)
#pragma unroll
            for (int k = 0; k < 4; ++k) acc[i][j][k] = 0.f;

    auto load_stage = [&](int s, int kt) {
        const float* ga = Ag + (size_t)kt * STAGE_FLOATS;
        const float* gb = Bg + (size_t)kt * STAGE_FLOATS;
#pragma unroll
        for (int i = 0; i < 4; ++i) {
            int idx = tid + i * 256;    // float4 index 0..1023
            unsigned sa = smem_u32(As + s * STAGE_FLOATS + idx * 4);
            asm volatile("cp.async.cg.shared.global [%0], [%1], 16;\n" :: "r"(sa), "l"(ga + idx * 4));
            unsigned sb = smem_u32(Bs + s * STAGE_FLOATS + idx * 4);
            asm volatile("cp.async.cg.shared.global [%0], [%1], 16;\n" :: "r"(sb), "l"(gb + idx * 4));
        }
        asm volatile("cp.async.commit_group;\n");
    };

    load_stage(0, 0);
    const int KT = CHANNELS / GBK;   // 32 stages
    for (int kt = 0; kt < KT; ++kt) {
        asm volatile("cp.async.wait_group 0;\n");
        __syncthreads();
        int cur = kt & 1;
        if (kt + 1 < KT) load_stage(cur ^ 1, kt + 1);
        const float* Ab = As + cur * STAGE_FLOATS;
        const float* Bb = Bs + cur * STAGE_FLOATS;
#pragma unroll
        for (int kk = 0; kk < 4; ++kk) {
            uint2 bf[4];
#pragma unroll
            for (int ni = 0; ni < 4; ++ni)
                bf[ni] = *(const uint2*)(Bb + ((kk * 16 + wn * 4 + ni) * 32 + lane) * 2);
#pragma unroll
            for (int mi = 0; mi < 4; ++mi) {
                uint4 af = *(const uint4*)(Ab + ((kk * 8 + wm * 4 + mi) * 32 + lane) * 4);
#pragma unroll
                for (int ni = 0; ni < 4; ++ni) {
                    asm volatile(
                        "mma.sync.aligned.m16n8k8.row.col.f32.tf32.tf32.f32 "
                        "{%0,%1,%2,%3}, {%4,%5,%6,%7}, {%8,%9}, {%0,%1,%2,%3};\n"
                        : "+f"(acc[mi][ni][0]), "+f"(acc[mi][ni][1]),
                          "+f"(acc[mi][ni][2]), "+f"(acc[mi][ni][3])
                        : "r"(af.x), "r"(af.y), "r"(af.z), "r"(af.w),
                          "r"(bf[ni].x), "r"(bf[ni].y));
                }
            }
        }
        __syncthreads();
    }

    // stash C tile in smem (reuse operand smem)
#pragma unroll
    for (int mi = 0; mi < 4; ++mi) {
#pragma unroll
        for (int ni = 0; ni < 4; ++ni) {
            int r0 = wm * 64 + mi * 16 + (lane >> 2);
            int c0 = wn * 32 + ni * 8 + (lane & 3) * 2;
            Cs[r0 * 132 + c0]           = acc[mi][ni][0];
            Cs[r0 * 132 + c0 + 1]       = acc[mi][ni][1];
            Cs[(r0 + 8) * 132 + c0]     = acc[mi][ni][2];
            Cs[(r0 + 8) * 132 + c0 + 1] = acc[mi][ni][3];
        }
    }
    __syncthreads();

    // 4x4 max pool + relu + x/sqrt(x^2+eps)
#pragma unroll
    for (int o = 0; o < 4; ++o) {
        int idx = tid * 4 + o;
        int pp = idx >> 5, qq = idx & 31;
        float m = -1e30f;
#pragma unroll
        for (int i = 0; i < 4; ++i)
#pragma unroll
            for (int j = 0; j < 4; ++j)
                m = fmaxf(m, Cs[(pp * 4 + i) * 132 + qq * 4 + j]);
        m = fmaxf(m, 0.f);
        float v = m * rsqrtf(m * m + EPS_L2);
        out[((size_t)b * POOL_P + blockIdx.y * 32 + pp) * POOL_P + blockIdx.x * 32 + qq] = v;
    }
}

// ---------------------------------------------------------------------------
// 4) row / col maxes on [b][576][576] (values are >= 0)
// ---------------------------------------------------------------------------
__global__ void rowmax_kernel(const float* __restrict__ X, float* __restrict__ amax) {
    int row = blockIdx.x, b = blockIdx.y;
    const float* p = X + ((size_t)b * POOL_P + row) * POOL_P;
    float m = 0.f;
    for (int q = threadIdx.x; q < POOL_P; q += 64) m = fmaxf(m, p[q]);
    __shared__ float red[64];
    red[threadIdx.x] = m;
    __syncthreads();
    if (threadIdx.x < 32) {
        m = fmaxf(red[threadIdx.x], red[threadIdx.x + 32]);
#pragma unroll
        for (int s = 16; s; s >>= 1) m = fmaxf(m, __shfl_down_sync(0xffffffffu, m, s));
        if (threadIdx.x == 0) amax[b * POOL_P + row] = m;
    }
}

__global__ void colmax_kernel(const float* __restrict__ X, float* __restrict__ bmax) {
    int q = blockIdx.x * 64 + threadIdx.x;
    int b = blockIdx.y;
    const float* p = X + (size_t)b * POOL_P * POOL_P + q;
    float m = 0.f;
#pragma unroll 8
    for (int r = 0; r < POOL_P; ++r) m = fmaxf(m, p[(size_t)r * POOL_P]);
    bmax[b * POOL_P + q] = m;
}

// ---------------------------------------------------------------------------
// 5) mutual matching: out = c * (c/(amax+eps)) * (c/(bmax+eps))
// ---------------------------------------------------------------------------
__global__ void mm_kernel(const float* __restrict__ X, const float* __restrict__ am,
                          const float* __restrict__ bm, float* __restrict__ O) {
    int i = blockIdx.x * blockDim.x + threadIdx.x;
    if (i >= POS_TOTAL) return;
    int q = i % POOL_P;
    int pr = (i / POOL_P) % POOL_P;
    int b = i / (POOL_P * POOL_P);
    float c = X[i];
    float r = c / (am[b * POOL_P + pr] + EPS_MM);
    float s = c / (bm[b * POOL_P + q] + EPS_MM);
    O[i] = c * r * s;
}

// ---------------------------------------------------------------------------
// 6) Conv4d 3^4 SAME + bias + relu.  Block = (x2, x1, b); 288 threads,
//    each thread computes 2 outputs along x4 for all Cout.
//    Inner math uses packed fma.rn.f32x2 over output-channel pairs.
// ---------------------------------------------------------------------------
template <int CIN, int COUT>
__global__ __launch_bounds__(288) void conv4d_relu_kernel(
    const float* __restrict__ in, const float* __restrict__ w,
    const float* __restrict__ bias, float* __restrict__ out) {
    constexpr int CP2 = (COUT % 2 == 0) ? COUT : COUT + 1;
    constexpr int COP = CP2 / 2;
    extern __shared__ float sm[];
    float* wsm = sm;                      // [CIN*81][CP2] (co-minor)
    float* pl = sm + CIN * 81 * CP2;      // [CIN][26][26]

    int tid = threadIdx.x;
    int b = blockIdx.z, x1 = blockIdx.y, x2 = blockIdx.x;

    for (int i = tid; i < CIN * 81 * CP2; i += 288) {
        int co = i % CP2;
        int rest = i / CP2;              // ci*81 + tap
        int ci = rest / 81, tap = rest % 81;
        wsm[i] = (co < COUT) ? w[(co * CIN + ci) * 81 + tap] : 0.f;
    }

    int x3 = tid / 12;
    int x4 = (tid % 12) * 2;

    u64 acc[COP][2];
#pragma unroll
    for (int cp = 0; cp < COP; ++cp) { acc[cp][0] = 0ull; acc[cp][1] = 0ull; }

    for (int j1 = 0; j1 < 3; ++j1) {
        int y1 = x1 + j1 - 1;
        for (int j2 = 0; j2 < 3; ++j2) {
            int y2 = x2 + j2 - 1;
            __syncthreads();
            bool pv = ((unsigned)y1 < 24u) && ((unsigned)y2 < 24u);
            for (int i2 = tid; i2 < CIN * 676; i2 += 288) {
                int ci = i2 / 676;
                int rem = i2 % 676;
                int rr = rem / 26, cc2 = rem % 26;
                int g3 = rr - 1, g4 = cc2 - 1;
                float v = 0.f;
                if (pv && (unsigned)g3 < 24u && (unsigned)g4 < 24u)
                    v = in[((((size_t)b * CIN + ci) * 24 + y1) * 24 + y2) * POOL_P + g3 * 24 + g4];
                pl[i2] = v;
            }
            __syncthreads();

            for (int ci = 0; ci < CIN; ++ci) {
#pragma unroll
                for (int j3 = 0; j3 < 3; ++j3) {
                    const float* vr = &pl[ci * 676 + (x3 + j3) * 26 + x4];
                    float v0 = vr[0], v1 = vr[1], v2 = vr[2], v3 = vr[3];
                    u64 vd[4] = {pack2(v0, v0), pack2(v1, v1), pack2(v2, v2), pack2(v3, v3)};
                    const float* wb = &wsm[(ci * 81 + j1 * 27 + j2 * 9 + j3 * 3) * CP2];
#pragma unroll
                    for (int j4 = 0; j4 < 3; ++j4) {
#pragma unroll
                        for (int cp = 0; cp < COP; ++cp) {
                            u64 wp = *reinterpret_cast<const u64*>(wb + j4 * CP2 + cp * 2);
                            fma2(acc[cp][0], wp, vd[j4]);
                            fma2(acc[cp][1], wp, vd[j4 + 1]);
                        }
                    }
                }
            }
        }
    }

    size_t obase = (((size_t)b * COUT * 24 + x1) * 24 + x2) * POOL_P + x3 * 24 + x4;
#pragma unroll
    for (int cp = 0; cp < COP; ++cp) {
        float2 p0 = unpack2(acc[cp][0]);   // (co0, co1) at x4
        float2 p1 = unpack2(acc[cp][1]);   // (co0, co1) at x4+1
        int co0 = 2 * cp, co1 = co0 + 1;
        float b0 = bias[co0];
        out[obase + (size_t)co0 * (24 * 24 * POOL_P)]     = fmaxf(p0.x + b0, 0.f);
        out[obase + (size_t)co0 * (24 * 24 * POOL_P) + 1] = fmaxf(p1.x + b0, 0.f);
        if (co1 < COUT) {
            float b1 = bias[co1];
            out[obase + (size_t)co1 * (24 * 24 * POOL_P)]     = fmaxf(p0.y + b1, 0.f);
            out[obase + (size_t)co1 * (24 * 24 * POOL_P) + 1] = fmaxf(p1.y + b1, 0.f);
        }
    }
}

// ---------------------------------------------------------------------------
// Launch
// ---------------------------------------------------------------------------
extern "C" void kernel_launch(void* const* d_in, const int* in_sizes, int n_in,
                              void* d_out, int out_size) {
    const float* fA = (const float*)d_in[0];
    const float* fB = (const float*)d_in[1];
    const float* w1 = (const float*)d_in[2];
    const float* b1 = (const float*)d_in[3];
    const float* w2 = (const float*)d_in[4];
    const float* b2 = (const float*)d_in[5];
    const float* w3 = (const float*)d_in[6];
    const float* b3 = (const float*)d_in[7];
    float* out = (float*)d_out;

    float *gA, *gB, *invA, *invB, *cpool, *x1b, *x2b, *amax, *bmax;
    cudaGetSymbolAddress((void**)&gA, g_A);
    cudaGetSymbolAddress((void**)&gB, g_B);
    cudaGetSymbolAddress((void**)&invA, g_invnA);
    cudaGetSymbolAddress((void**)&invB, g_invnB);
    cudaGetSymbolAddress((void**)&cpool, g_cpool);
    cudaGetSymbolAddress((void**)&x1b, g_x1);
    cudaGetSymbolAddress((void**)&x2b, g_x2);
    cudaGetSymbolAddress((void**)&amax, g_amax);
    cudaGetSymbolAddress((void**)&bmax, g_bmax);

    cudaFuncSetAttribute(gemm_pool_kernel, cudaFuncAttributeMaxDynamicSharedMemorySize, 69632);
    cudaFuncSetAttribute(conv4d_relu_kernel<10, 10>, cudaFuncAttributeMaxDynamicSharedMemorySize, 61440);

    // 1) inverse norms
    invnorm_kernel<<<(2 * BATCH * HW) / 256, 256>>>(fA, fB);

    // 2) transpose + normalize + tf32 round into fragment-ordered layouts
    dim3 tgrid(72, 32, BATCH);
    transnorm_kernel<0><<<tgrid, 256>>>(fA, invA, gA);
    transnorm_kernel<1><<<tgrid, 256>>>(fB, invB, gB);

    // 3) TF32 GEMM + pool + relu/L2
    gemm_pool_kernel<<<dim3(18, 18, BATCH), 256, 69632>>>(gA, gB, cpool);

    // 4) mutual matching #1 (in place)
    rowmax_kernel<<<dim3(POOL_P, BATCH), 64>>>(cpool, amax);
    colmax_kernel<<<dim3(POOL_P / 64, BATCH), 64>>>(cpool, bmax);
    mm_kernel<<<(POS_TOTAL + 255) / 256, 256>>>(cpool, amax, bmax, cpool);

    // 5) neighbourhood consensus convs
    dim3 cgrid(24, 24, BATCH);
    size_t sm1 = (size_t)(1 * 81 * 10 + 1 * 676) * 4;
    size_t sm2 = (size_t)(10 * 81 * 10 + 10 * 676) * 4;
    size_t sm3 = (size_t)(10 * 81 * 2 + 10 * 676) * 4;
    conv4d_relu_kernel<1, 10><<<cgrid, 288, sm1>>>(cpool, w1, b1, x1b);
    conv4d_relu_kernel<10, 10><<<cgrid, 288, sm2>>>(x1b, w2, b2, x2b);
    conv4d_relu_kernel<10, 1><<<cgrid, 288, sm3>>>(x2b, w3, b3, cpool);

    // 6) mutual matching #2 -> output
    rowmax_kernel<<<dim3(POOL_P, BATCH), 64>>>(cpool, amax);
    colmax_kernel<<<dim3(POOL_P / 64, BATCH), 64>>>(cpool, bmax);
    mm_kernel<<<(POS_TOTAL + 255) / 256, 256>>>(cpool, amax, bmax, out);

    (void)in_sizes; (void)n_in; (void)out_size;
}